// round 5
// baseline (speedup 1.0000x reference)
#include <cuda_runtime.h>
#include <math.h>

#define H  1024
#define ML 4096
#define V  128000

// ------------------------- device scratch -------------------------
__device__ float    g_alog[ML];            // attention logits
__device__ float    g_aw[ML];              // attention weights (softmax)
__device__ float    g_ctx_part[32][H];     // split-K partials for context
__device__ float    g_cat2[2 * H];         // [e0, ctx]
__device__ float    g_x[H];                // relu(combine)
__device__ float    g_gi[3 * H];
__device__ float    g_gh[3 * H];
__device__ float    g_hnew[H];
__device__ float    g_blog[V];             // vocab logits
__device__ unsigned g_maxbits;             // order-flipped float max
__device__ float    g_psum[512];           // sum-exp partials
__device__ float    g_lse;                 // max + log(sumexp)
__device__ unsigned g_cnt[8];              // self-resetting last-block counters (zero-init)

// ------------------------- helpers -------------------------
__device__ __forceinline__ float wsum(float v) {
#pragma unroll
    for (int o = 16; o; o >>= 1) v += __shfl_xor_sync(0xffffffffu, v, o);
    return v;
}
__device__ __forceinline__ float wmax(float v) {
#pragma unroll
    for (int o = 16; o; o >>= 1) v = fmaxf(v, __shfl_xor_sync(0xffffffffu, v, o));
    return v;
}
__device__ __forceinline__ unsigned fflip(float f) {
    unsigned u = __float_as_uint(f);
    return (u & 0x80000000u) ? ~u : (u | 0x80000000u);
}
__device__ __forceinline__ float funflip(unsigned u) {
    return __uint_as_float((u & 0x80000000u) ? (u ^ 0x80000000u) : ~u);
}
__device__ __forceinline__ float dot4(float4 a, float4 b) {
    return a.x * b.x + a.y * b.y + a.z * b.z + a.w * b.w;
}
__device__ __forceinline__ void add4(float4& a, float4 b) {
    a.x += b.x; a.y += b.y; a.z += b.z; a.w += b.w;
}
// returns true in exactly the last-arriving block; counter self-resets to 0
__device__ __forceinline__ bool last_block(unsigned* cnt, unsigned nblocks) {
    __threadfence();
    return atomicInc(cnt, nblocks - 1u) == nblocks - 1u;
}

// ========================= KA: attn logits + fused softmax =========================
// grid 512 x 256: 8 rows/block matvec; last block does softmax over ML
__global__ void ka_attn(const int* __restrict__ ids, const float* __restrict__ hidden,
                        const float* __restrict__ emb,
                        const float* __restrict__ attn_w, const float* __restrict__ attn_b,
                        float* __restrict__ out_aw) {
    __shared__ float4 sv[512];
    __shared__ unsigned sLast;
    __shared__ float red[8];
    __shared__ float sM, sS;
    int t = threadIdx.x;
    int id = ids[0];
    const float4* e4 = (const float4*)(emb + (long)id * H);
    const float4* h4 = (const float4*)hidden;
    for (int i = t; i < 512; i += 256) sv[i] = (i < 256) ? e4[i] : h4[i - 256];
    if (blockIdx.x == 0 && t == 0) g_maxbits = 0u;   // reset vocab running max
    __syncthreads();
    int warp = t >> 5, lane = t & 31;
    int row = blockIdx.x * 8 + warp;
    const float4* w4 = (const float4*)(attn_w + (long)row * 2048);
    float acc = 0.f;
#pragma unroll
    for (int i = 0; i < 16; i++)
        acc += dot4(__ldcs(&w4[lane + i * 32]), sv[lane + i * 32]);
    acc = wsum(acc);
    if (lane == 0) { g_alog[row] = acc + attn_b[row]; __threadfence(); }
    __syncthreads();
    if (t == 0) sLast = last_block(&g_cnt[0], gridDim.x) ? 1u : 0u;
    __syncthreads();
    if (!sLast) return;

    // ---- softmax over 4096 with 256 threads (16 elems/thread, coalesced) ----
    float v[16];
    float m = -1e30f;
#pragma unroll
    for (int i = 0; i < 16; i++) { v[i] = g_alog[t + i * 256]; m = fmaxf(m, v[i]); }
    m = wmax(m);
    if (lane == 0) red[warp] = m;
    __syncthreads();
    if (t == 0) {
        float x = red[0];
#pragma unroll
        for (int i = 1; i < 8; i++) x = fmaxf(x, red[i]);
        sM = x;
    }
    __syncthreads();
    float M = sM, s = 0.f;
#pragma unroll
    for (int i = 0; i < 16; i++) { v[i] = expf(v[i] - M); s += v[i]; }
    s = wsum(s);
    if (lane == 0) red[warp] = s;
    __syncthreads();
    if (t == 0) {
        float x = 0.f;
#pragma unroll
        for (int i = 0; i < 8; i++) x += red[i];
        sS = x;
    }
    __syncthreads();
    float inv = 1.f / sS;
#pragma unroll
    for (int i = 0; i < 16; i++) {
        float w = v[i] * inv;
        g_aw[t + i * 256]   = w;
        out_aw[t + i * 256] = w;
    }
}

// ========================= KB: context split-K + fused final reduce =========================
// grid 256 = 32 chunks x 8 col-groups; last block reduces 32 chunks + copies e0
__global__ void kb_ctx(const float* __restrict__ enc,
                       const int* __restrict__ ids, const float* __restrict__ emb) {
    __shared__ float4 sp[8][32];
    __shared__ unsigned sLast;
    int t = threadIdx.x;
    int chunk = blockIdx.x >> 3;
    int g     = blockIdx.x & 7;
    int c     = t & 31;
    int phase = t >> 5;
    int col   = g * 32 + c;
    const float4* e4 = (const float4*)enc;
    int r0 = chunk * 128 + phase * 16;
    float4 acc = make_float4(0.f, 0.f, 0.f, 0.f);
#pragma unroll
    for (int k = 0; k < 16; k++) {
        float w = g_aw[r0 + k];
        float4 v = __ldcs(&e4[(long)(r0 + k) * 256 + col]);
        acc.x += w * v.x; acc.y += w * v.y; acc.z += w * v.z; acc.w += w * v.w;
    }
    sp[phase][c] = acc;
    __syncthreads();
    if (phase == 0) {
        float4 s = acc;
#pragma unroll
        for (int p = 1; p < 8; p++) add4(s, sp[p][c]);
        ((float4*)g_ctx_part)[chunk * 256 + col] = s;
        __threadfence();
    }
    __syncthreads();
    if (t == 0) sLast = last_block(&g_cnt[1], gridDim.x) ? 1u : 0u;
    __syncthreads();
    if (!sLast) return;

    // e0 copy (256 f4) + ctx reduce (each thread one f4 col, 32 chunk loads)
    ((float4*)g_cat2)[t] = ((const float4*)(emb + (long)ids[0] * H))[t];
    const float4* p4 = (const float4*)g_ctx_part;
    float4 s = make_float4(0.f, 0.f, 0.f, 0.f);
#pragma unroll
    for (int k = 0; k < 32; k++) add4(s, p4[(long)k * 256 + t]);
    ((float4*)(g_cat2 + H))[t] = s;
}

// ========================= KC1: comb matvec (x) || gh matvec =========================
// blocks 0..127: x = relu(comb_w @ cat2 + comb_b), 8 rows/block
// blocks 128..319: gh = w_hh @ hidden + b_hh, 16 rows/block (2/warp)
__global__ void kc1(const float* __restrict__ comb_w, const float* __restrict__ comb_b,
                    const float* __restrict__ w_hh, const float* __restrict__ b_hh,
                    const float* __restrict__ hidden) {
    int t = threadIdx.x;
    int warp = t >> 5, lane = t & 31;
    if (blockIdx.x < 128) {
        __shared__ float4 sv[512];
        const float4* c4 = (const float4*)g_cat2;
        for (int i = t; i < 512; i += 256) sv[i] = c4[i];
        __syncthreads();
        int row = blockIdx.x * 8 + warp;
        const float4* w4 = (const float4*)(comb_w + (long)row * 2048);
        float acc = 0.f;
#pragma unroll
        for (int i = 0; i < 16; i++)
            acc += dot4(__ldcs(&w4[lane + i * 32]), sv[lane + i * 32]);
        acc = wsum(acc);
        if (lane == 0) g_x[row] = fmaxf(acc + comb_b[row], 0.f);
    } else {
        __shared__ float4 sh[256];
        sh[t] = ((const float4*)hidden)[t];
        __syncthreads();
        int r = (blockIdx.x - 128) * 16 + warp * 2;   // 0..3071
        const float4* w0 = (const float4*)(w_hh + (long)r * H);
        const float4* w1 = (const float4*)(w_hh + (long)(r + 1) * H);
        float a0 = 0.f, a1 = 0.f;
#pragma unroll
        for (int i = 0; i < 8; i++) {
            float4 b = sh[lane + i * 32];
            a0 += dot4(__ldcs(&w0[lane + i * 32]), b);
            a1 += dot4(__ldcs(&w1[lane + i * 32]), b);
        }
        a0 = wsum(a0); a1 = wsum(a1);
        if (lane == 0) { g_gh[r] = a0 + b_hh[r]; g_gh[r + 1] = a1 + b_hh[r + 1]; }
    }
}

// ========================= KC2: gi matvec + fused GRU combine =========================
// grid 192: 16 rows/block (2/warp) of gi = w_ih @ x + b_ih; last block does GRU
__global__ void kc2(const float* __restrict__ w_ih, const float* __restrict__ b_ih,
                    const float* __restrict__ hidden, float* __restrict__ out_h) {
    __shared__ float4 sx[256];
    __shared__ unsigned sLast;
    int t = threadIdx.x;
    int warp = t >> 5, lane = t & 31;
    sx[t] = ((const float4*)g_x)[t];
    __syncthreads();
    int r = blockIdx.x * 16 + warp * 2;   // 0..3071
    const float4* w0 = (const float4*)(w_ih + (long)r * H);
    const float4* w1 = (const float4*)(w_ih + (long)(r + 1) * H);
    float a0 = 0.f, a1 = 0.f;
#pragma unroll
    for (int i = 0; i < 8; i++) {
        float4 b = sx[lane + i * 32];
        a0 += dot4(__ldcs(&w0[lane + i * 32]), b);
        a1 += dot4(__ldcs(&w1[lane + i * 32]), b);
    }
    a0 = wsum(a0); a1 = wsum(a1);
    if (lane == 0) {
        g_gi[r] = a0 + b_ih[r];
        g_gi[r + 1] = a1 + b_ih[r + 1];
        __threadfence();
    }
    __syncthreads();
    if (t == 0) sLast = last_block(&g_cnt[2], gridDim.x) ? 1u : 0u;
    __syncthreads();
    if (!sLast) return;

    // GRU combine: 1024 elems, 4 per thread
#pragma unroll
    for (int k = 0; k < 4; k++) {
        int j = t + k * 256;
        float rr = 1.f / (1.f + expf(-(g_gi[j] + g_gh[j])));
        float z  = 1.f / (1.f + expf(-(g_gi[H + j] + g_gh[H + j])));
        float n  = tanhf(g_gi[2 * H + j] + rr * g_gh[2 * H + j]);
        float h  = (1.f - z) * n + z * hidden[j];
        g_hnew[j] = h;
        out_h[j]  = h;
    }
}

// ========================= K7: vocab logits + running max (512 MB stream) =========================
__global__ void k7_logits(const float* __restrict__ out_w, const float* __restrict__ out_b) {
    __shared__ float4 sh[256];
    __shared__ float red[16];
    int t = threadIdx.x;
    sh[t] = ((const float4*)g_hnew)[t];
    __syncthreads();
    int warp = t >> 5, lane = t & 31;
    int row = blockIdx.x * 16 + warp * 2;
    const float4* w0 = (const float4*)(out_w + (long)row * H);
    const float4* w1 = (const float4*)(out_w + (long)(row + 1) * H);
    float a0 = 0.f, a1 = 0.f;
#pragma unroll
    for (int i = 0; i < 8; i++) {
        float4 b = sh[lane + i * 32];
        a0 += dot4(__ldcs(&w0[lane + i * 32]), b);
        a1 += dot4(__ldcs(&w1[lane + i * 32]), b);
    }
    a0 = wsum(a0); a1 = wsum(a1);
    float l0 = a0 + out_b[row];
    float l1 = a1 + out_b[row + 1];
    if (lane == 0) {
        g_blog[row]     = l0;
        g_blog[row + 1] = l1;
        red[warp * 2]     = l0;
        red[warp * 2 + 1] = l1;
    }
    __syncthreads();
    if (t == 0) {
        float m = red[0];
#pragma unroll
        for (int i = 1; i < 16; i++) m = fmaxf(m, red[i]);
        atomicMax(&g_maxbits, fflip(m));  // max commutative -> deterministic
    }
}

// ========================= KE1: sum-exp partials + fused LSE =========================
// grid 512; fixed-slot partials; last block reduces 512 -> g_lse
__global__ void ke1_psum() {
    __shared__ float red[8];
    __shared__ unsigned sLast;
    int t = threadIdx.x;
    int warp = t >> 5, lane = t & 31;
    float M = funflip(g_maxbits);
    int base = blockIdx.x * 250;  // 512 * 250 = 128000
    float acc = (t < 250) ? expf(g_blog[base + t] - M) : 0.f;
    acc = wsum(acc);
    if (lane == 0) red[warp] = acc;
    __syncthreads();
    if (t == 0) {
        float s = 0.f;
#pragma unroll
        for (int i = 0; i < 8; i++) s += red[i];
        g_psum[blockIdx.x] = s;
        __threadfence();
        sLast = last_block(&g_cnt[3], gridDim.x) ? 1u : 0u;
    }
    __syncthreads();
    if (!sLast) return;

    float v = g_psum[t] + g_psum[t + 256];
    v = wsum(v);
    if (lane == 0) red[warp] = v;
    __syncthreads();
    if (t == 0) {
        float s = 0.f;
#pragma unroll
        for (int i = 0; i < 8; i++) s += red[i];
        g_lse = M + logf(s);
    }
}

// ========================= KE2: write log-softmax =========================
__global__ void ke2_out(float* __restrict__ out) {
    int v = blockIdx.x * 256 + threadIdx.x;  // grid 500
    out[v] = g_blog[v] - g_lse;
}

// ------------------------- launch -------------------------
extern "C" void kernel_launch(void* const* d_in, const int* in_sizes, int n_in,
                              void* d_out, int out_size) {
    const int*   ids    = (const int*)d_in[0];
    const float* hidden = (const float*)d_in[1];
    const float* enc    = (const float*)d_in[2];
    const float* emb    = (const float*)d_in[3];
    const float* attn_w = (const float*)d_in[4];
    const float* attn_b = (const float*)d_in[5];
    const float* comb_w = (const float*)d_in[6];
    const float* comb_b = (const float*)d_in[7];
    const float* w_ih   = (const float*)d_in[8];
    const float* w_hh   = (const float*)d_in[9];
    const float* b_ih   = (const float*)d_in[10];
    const float* b_hh   = (const float*)d_in[11];
    const float* out_w  = (const float*)d_in[12];
    const float* out_b  = (const float*)d_in[13];
    float* out = (float*)d_out;

    ka_attn<<<512, 256>>>(ids, hidden, emb, attn_w, attn_b, out + V + H);
    kb_ctx<<<256, 256>>>(enc, ids, emb);
    kc1<<<320, 256>>>(comb_w, comb_b, w_hh, b_hh, hidden);
    kc2<<<192, 256>>>(w_ih, b_ih, hidden, out + V);
    k7_logits<<<8000, 256>>>(out_w, out_b);
    ke1_psum<<<512, 256>>>();
    ke2_out<<<500, 256>>>(out);
}

// round 6
// speedup vs baseline: 1.0729x; 1.0729x over previous
#include <cuda_runtime.h>
#include <math.h>

#define H  1024
#define ML 4096
#define V  128000

// ------------------------- device scratch -------------------------
__device__ float    g_alog[ML];            // attention logits
__device__ float    g_aw[ML];              // attention weights (softmax)
__device__ float    g_ctx_part[32][H];     // split-K partials for context
__device__ float    g_cat2[2 * H];         // [e0, ctx]
__device__ float    g_x[H];                // relu(combine)
__device__ float    g_gi[3 * H];
__device__ float    g_gh[3 * H];
__device__ float    g_hnew[H];
__device__ float    g_blog[V];             // vocab logits
__device__ unsigned g_maxbits;             // order-flipped float max
__device__ float    g_psum[512];           // sum-exp partials
__device__ float    g_lse;                 // max + log(sumexp)

// ------------------------- helpers -------------------------
__device__ __forceinline__ float wsum(float v) {
#pragma unroll
    for (int o = 16; o; o >>= 1) v += __shfl_xor_sync(0xffffffffu, v, o);
    return v;
}
__device__ __forceinline__ float wmax(float v) {
#pragma unroll
    for (int o = 16; o; o >>= 1) v = fmaxf(v, __shfl_xor_sync(0xffffffffu, v, o));
    return v;
}
__device__ __forceinline__ unsigned fflip(float f) {
    unsigned u = __float_as_uint(f);
    return (u & 0x80000000u) ? ~u : (u | 0x80000000u);
}
__device__ __forceinline__ float funflip(unsigned u) {
    return __uint_as_float((u & 0x80000000u) ? (u ^ 0x80000000u) : ~u);
}
__device__ __forceinline__ float dot4(float4 a, float4 b) {
    return a.x * b.x + a.y * b.y + a.z * b.z + a.w * b.w;
}
__device__ __forceinline__ void add4(float4& a, float4 b) {
    a.x += b.x; a.y += b.y; a.z += b.z; a.w += b.w;
}
// block-reduce 256 partial sums (fixed order -> deterministic); result valid in t==0
__device__ __forceinline__ float block_reduce256(float acc, float* red8) {
    int warp = threadIdx.x >> 5, lane = threadIdx.x & 31;
    acc = wsum(acc);
    if (lane == 0) red8[warp] = acc;
    __syncthreads();
    float s = 0.f;
    if (threadIdx.x == 0) {
#pragma unroll
        for (int i = 0; i < 8; i++) s += red8[i];
    }
    return s;
}

// ------------------------- K1: attention logits, block-per-row (grid 4096) -------------------------
__global__ void k1_attn(const int* __restrict__ ids, const float* __restrict__ hidden,
                        const float* __restrict__ emb,
                        const float* __restrict__ attn_w, const float* __restrict__ attn_b) {
    __shared__ float red8[8];
    int t = threadIdx.x;
    int row = blockIdx.x;
    int id = ids[0];
    const float4* e4 = (const float4*)(emb + (long)id * H);
    const float4* h4 = (const float4*)hidden;
    const float4* w4 = (const float4*)(attn_w + (long)row * 2048);
    // cols [0,1024): e0 ; cols [1024,2048): h0   (f4 indices 0..255 / 256..511)
    float acc = dot4(w4[t], e4[t]) + dot4(w4[t + 256], h4[t]);
    float s = block_reduce256(acc, red8);
    if (t == 0) g_alog[row] = s + attn_b[row];
}

// ------------------------- K2: softmax over ML=4096 (one block, 1024 threads) -------------------------
__global__ void k2_softmax(float* __restrict__ out_aw) {
    __shared__ float red[32];
    __shared__ float smax, ssum;
    int t = threadIdx.x;
    if (t == 0) g_maxbits = 0u;   // reset vocab running max (graph-replay safe)
    float v[4];
#pragma unroll
    for (int i = 0; i < 4; i++) v[i] = g_alog[t + i * 1024];
    float m = fmaxf(fmaxf(v[0], v[1]), fmaxf(v[2], v[3]));
    m = wmax(m);
    if ((t & 31) == 0) red[t >> 5] = m;
    __syncthreads();
    if (t < 32) { float x = red[t]; x = wmax(x); if (t == 0) smax = x; }
    __syncthreads();
    float M = smax;
    float s = 0.f;
#pragma unroll
    for (int i = 0; i < 4; i++) { v[i] = expf(v[i] - M); s += v[i]; }
    s = wsum(s);
    if ((t & 31) == 0) red[t >> 5] = s;
    __syncthreads();
    if (t < 32) { float x = red[t]; x = wsum(x); if (t == 0) ssum = x; }
    __syncthreads();
    float inv = 1.f / ssum;
#pragma unroll
    for (int i = 0; i < 4; i++) {
        float w = v[i] * inv;
        g_aw[t + i * 1024]   = w;
        out_aw[t + i * 1024] = w;
    }
}

// ------------------------- K3: context split-K with in-block reduction -------------------------
// grid 256 = 32 chunks x 8 col-groups; block reduces its 128 rows internally
__global__ void k3_ctx(const float* __restrict__ enc) {
    __shared__ float4 sp[8][32];
    int t = threadIdx.x;
    int chunk = blockIdx.x >> 3;
    int g     = blockIdx.x & 7;
    int c     = t & 31;
    int phase = t >> 5;
    int col   = g * 32 + c;
    const float4* e4 = (const float4*)enc;
    int r0 = chunk * 128 + phase * 16;
    float4 acc = make_float4(0.f, 0.f, 0.f, 0.f);
#pragma unroll
    for (int k = 0; k < 16; k++) {
        float w = g_aw[r0 + k];
        float4 v = e4[(long)(r0 + k) * 256 + col];
        acc.x += w * v.x; acc.y += w * v.y; acc.z += w * v.z; acc.w += w * v.w;
    }
    sp[phase][c] = acc;
    __syncthreads();
    if (phase == 0) {
        float4 s = acc;
#pragma unroll
        for (int p = 1; p < 8; p++) add4(s, sp[p][c]);
        ((float4*)g_ctx_part)[chunk * 256 + col] = s;
    }
}

// ------------------------- K4a: final reduce + build cat2 = [e0, ctx] -------------------------
// grid 9: blocks 0-7 reduce 32 chunks for 32 f4-cols each; block 8 copies e0
__global__ void k4a_cat2(const int* __restrict__ ids, const float* __restrict__ emb) {
    int t = threadIdx.x;
    if (blockIdx.x == 8) {
        ((float4*)g_cat2)[t] = ((const float4*)(emb + (long)ids[0] * H))[t];
        return;
    }
    __shared__ float4 sp[8][32];
    int c = t & 31, phase = t >> 5;
    int col = blockIdx.x * 32 + c;
    const float4* p4 = (const float4*)g_ctx_part;
    float4 acc = make_float4(0.f, 0.f, 0.f, 0.f);
#pragma unroll
    for (int k = 0; k < 4; k++)
        add4(acc, p4[(long)(phase * 4 + k) * 256 + col]);
    sp[phase][c] = acc;
    __syncthreads();
    if (phase == 0) {
        float4 s = acc;
#pragma unroll
        for (int p = 1; p < 8; p++) add4(s, sp[p][c]);
        ((float4*)(g_cat2 + H))[col] = s;
    }
}

// ------------------------- K4b: x = relu(comb_w @ cat2 + comb_b), block-per-row (grid 1024) -------------------------
__global__ void k4b_x(const float* __restrict__ comb_w, const float* __restrict__ comb_b) {
    __shared__ float red8[8];
    int t = threadIdx.x;
    int row = blockIdx.x;
    const float4* c4 = (const float4*)g_cat2;
    const float4* w4 = (const float4*)(comb_w + (long)row * 2048);
    float acc = dot4(w4[t], c4[t]) + dot4(w4[t + 256], c4[t + 256]);
    float s = block_reduce256(acc, red8);
    if (t == 0) g_x[row] = fmaxf(s + comb_b[row], 0.f);
}

// ------------------------- K5: GRU gate matvecs, block-per-row (grid 6144) -------------------------
__global__ void k5_gates(const float* __restrict__ w_ih, const float* __restrict__ w_hh,
                         const float* __restrict__ b_ih, const float* __restrict__ b_hh,
                         const float* __restrict__ hidden) {
    __shared__ float red8[8];
    int t = threadIdx.x;
    int row = blockIdx.x;             // 0..6143
    const float4* w4;
    const float4* v4;
    float*        out;
    const float*  bias;
    int r;
    if (row < 3072) { r = row;        w4 = (const float4*)(w_ih + (long)r * H); v4 = (const float4*)g_x;   out = g_gi; bias = b_ih; }
    else            { r = row - 3072; w4 = (const float4*)(w_hh + (long)r * H); v4 = (const float4*)hidden; out = g_gh; bias = b_hh; }
    float acc = dot4(w4[t], v4[t]);
    float s = block_reduce256(acc, red8);
    if (t == 0) out[r] = s + bias[r];
}

// ------------------------- K6: GRU combine -------------------------
__global__ void k6_gru(const float* __restrict__ hidden, float* __restrict__ out_h) {
    int j = blockIdx.x * 256 + threadIdx.x;  // grid 4
    float r = 1.f / (1.f + expf(-(g_gi[j] + g_gh[j])));
    float z = 1.f / (1.f + expf(-(g_gi[H + j] + g_gh[H + j])));
    float n = tanhf(g_gi[2 * H + j] + r * g_gh[2 * H + j]);
    float h = (1.f - z) * n + z * hidden[j];
    g_hnew[j] = h;
    out_h[j]  = h;
}

// ------------------------- K7: vocab logits + running max (512 MB stream) -------------------------
// 2 rows/warp, 16 rows/block, grid 8000; __ldcs ONLY here (one-shot stream)
__global__ void k7_logits(const float* __restrict__ out_w, const float* __restrict__ out_b) {
    __shared__ float4 sh[256];
    __shared__ float red[16];
    int t = threadIdx.x;
    sh[t] = ((const float4*)g_hnew)[t];
    __syncthreads();
    int warp = t >> 5, lane = t & 31;
    int row = blockIdx.x * 16 + warp * 2;
    const float4* w0 = (const float4*)(out_w + (long)row * H);
    const float4* w1 = (const float4*)(out_w + (long)(row + 1) * H);
    float a0 = 0.f, a1 = 0.f;
#pragma unroll
    for (int i = 0; i < 8; i++) {
        float4 b = sh[lane + i * 32];
        a0 += dot4(__ldcs(&w0[lane + i * 32]), b);
        a1 += dot4(__ldcs(&w1[lane + i * 32]), b);
    }
    a0 = wsum(a0); a1 = wsum(a1);
    float l0 = a0 + out_b[row];
    float l1 = a1 + out_b[row + 1];
    if (lane == 0) {
        g_blog[row]       = l0;
        g_blog[row + 1]   = l1;
        red[warp * 2]     = l0;
        red[warp * 2 + 1] = l1;
    }
    __syncthreads();
    if (t == 0) {
        float m = red[0];
#pragma unroll
        for (int i = 1; i < 16; i++) m = fmaxf(m, red[i]);
        atomicMax(&g_maxbits, fflip(m));  // max commutative -> deterministic
    }
}

// ------------------------- K8: sum-exp partials (fixed slots -> deterministic) -------------------------
__global__ void k8_psum() {
    __shared__ float red[8];
    int t = threadIdx.x;
    float M = funflip(g_maxbits);
    int base = blockIdx.x * 250;  // 512 * 250 = 128000
    float acc = (t < 250) ? expf(g_blog[base + t] - M) : 0.f;
    acc = wsum(acc);
    if ((t & 31) == 0) red[t >> 5] = acc;
    __syncthreads();
    if (t == 0) {
        float s = 0.f;
#pragma unroll
        for (int i = 0; i < 8; i++) s += red[i];
        g_psum[blockIdx.x] = s;
    }
}

// ------------------------- K9: final log-sum-exp -------------------------
__global__ void k9_lse() {
    __shared__ float red[16];
    int t = threadIdx.x;  // 512
    float v = g_psum[t];
    v = wsum(v);
    if ((t & 31) == 0) red[t >> 5] = v;
    __syncthreads();
    if (t == 0) {
        float s = 0.f;
#pragma unroll
        for (int i = 0; i < 16; i++) s += red[i];
        g_lse = funflip(g_maxbits) + logf(s);
    }
}

// ------------------------- K10: write log-softmax -------------------------
__global__ void k10_out(float* __restrict__ out) {
    int v = blockIdx.x * 256 + threadIdx.x;  // grid 500
    out[v] = g_blog[v] - g_lse;
}

// ------------------------- launch -------------------------
extern "C" void kernel_launch(void* const* d_in, const int* in_sizes, int n_in,
                              void* d_out, int out_size) {
    const int*   ids    = (const int*)d_in[0];
    const float* hidden = (const float*)d_in[1];
    const float* enc    = (const float*)d_in[2];
    const float* emb    = (const float*)d_in[3];
    const float* attn_w = (const float*)d_in[4];
    const float* attn_b = (const float*)d_in[5];
    const float* comb_w = (const float*)d_in[6];
    const float* comb_b = (const float*)d_in[7];
    const float* w_ih   = (const float*)d_in[8];
    const float* w_hh   = (const float*)d_in[9];
    const float* b_ih   = (const float*)d_in[10];
    const float* b_hh   = (const float*)d_in[11];
    const float* out_w  = (const float*)d_in[12];
    const float* out_b  = (const float*)d_in[13];
    float* out = (float*)d_out;

    k1_attn<<<4096, 256>>>(ids, hidden, emb, attn_w, attn_b);
    k2_softmax<<<1, 1024>>>(out + V + H);
    k3_ctx<<<256, 256>>>(enc);
    k4a_cat2<<<9, 256>>>(ids, emb);
    k4b_x<<<1024, 256>>>(comb_w, comb_b);
    k5_gates<<<6144, 256>>>(w_ih, w_hh, b_ih, b_hh, hidden);
    k6_gru<<<4, 256>>>(hidden, out + V);
    k7_logits<<<8000, 256>>>(out_w, out_b);
    k8_psum<<<512, 256>>>();
    k9_lse<<<1, 512>>>();
    k10_out<<<500, 256>>>(out);
}